// round 3
// baseline (speedup 1.0000x reference)
#include <cuda_runtime.h>
#include <cuda_bf16.h>
#include <math.h>

// Problem constants
#define BATCH   8
#define HH      64
#define WW_     64
#define DIM     512
#define NHEAD   16
#define DK      32
#define WS      8
#define SHIFT   4
#define LAYERS  4
#define NTOK    (BATCH * HH * WW_)          // 32768
#define TBL     225                          // (2*WS-1)^2

// ---------------- scratch (device globals; no allocation allowed) ----------
__device__ float g_x  [NTOK * DIM];          // running state       64 MB
__device__ float g_xn [NTOK * DIM];          // layernorm output    64 MB
__device__ float g_q  [NTOK * DIM];          // Q                   64 MB
__device__ float g_kv [NTOK * 2 * DIM];      // K|V                128 MB
__device__ float g_at [NTOK * DIM];          // attention out       64 MB
__device__ float g_h  [NTOK * 4 * DIM];      // MLP hidden         256 MB

// ---------------- LayerNorm: one block per token, 128 threads --------------
__global__ __launch_bounds__(128) void ln_kernel(
    const float* __restrict__ x, const float* __restrict__ g,
    const float* __restrict__ b, float* __restrict__ y)
{
    int tok = blockIdx.x;
    const float* xp = x + (size_t)tok * DIM;
    float*       yp = y + (size_t)tok * DIM;
    int tid = threadIdx.x;

    float v[4];
    float s = 0.f;
#pragma unroll
    for (int i = 0; i < 4; i++) { v[i] = xp[tid + i * 128]; s += v[i]; }

    __shared__ float red1[4], red2[4];
#pragma unroll
    for (int o = 16; o > 0; o >>= 1) s += __shfl_xor_sync(0xffffffffu, s, o);
    if ((tid & 31) == 0) red1[tid >> 5] = s;
    __syncthreads();
    float mean = (red1[0] + red1[1] + red1[2] + red1[3]) * (1.f / DIM);

    float s2 = 0.f;
#pragma unroll
    for (int i = 0; i < 4; i++) { float d = v[i] - mean; s2 += d * d; }
#pragma unroll
    for (int o = 16; o > 0; o >>= 1) s2 += __shfl_xor_sync(0xffffffffu, s2, o);
    if ((tid & 31) == 0) red2[tid >> 5] = s2;
    __syncthreads();
    float var  = (red2[0] + red2[1] + red2[2] + red2[3]) * (1.f / DIM);
    float rstd = rsqrtf(var + 1e-5f);

#pragma unroll
    for (int i = 0; i < 4; i++) {
        int c = tid + i * 128;
        yp[c] = (v[i] - mean) * rstd * g[c] + b[c];
    }
}

// ---------------- SGEMM: C[M,N] = A[M,K] @ B[K,N] + bias (+res | gelu) -----
// BM=64, BN=64, BK=16, 256 threads, 4x4 microtile.
#define GBM 64
#define GBN 64
#define GBK 16
#define EPI_BIAS 0
#define EPI_RES  1
#define EPI_GELU 2

__global__ __launch_bounds__(256) void gemm_kernel(
    const float* __restrict__ A, const float* __restrict__ Bm,
    const float* __restrict__ bias, const float* __restrict__ res,
    float* __restrict__ C, int M, int N, int K, int epi)
{
    __shared__ float As[GBK][GBM];
    __shared__ float Bs[GBK][GBN];
    int bn = blockIdx.x * GBN;
    int bm = blockIdx.y * GBM;
    int tid = threadIdx.x;
    int tx = tid & 15, ty = tid >> 4;

    float acc[4][4] = {};
    for (int k0 = 0; k0 < K; k0 += GBK) {
#pragma unroll
        for (int i = 0; i < 4; i++) {                  // A tile: 64x16
            int idx = tid + i * 256;
            int r = idx >> 4, c = idx & 15;
            As[c][r] = A[(size_t)(bm + r) * K + k0 + c];
        }
#pragma unroll
        for (int i = 0; i < 4; i++) {                  // B tile: 16x64
            int idx = tid + i * 256;
            int r = idx >> 6, c = idx & 63;
            Bs[r][c] = Bm[(size_t)(k0 + r) * N + bn + c];
        }
        __syncthreads();
#pragma unroll
        for (int k = 0; k < GBK; k++) {
            float ra[4], rb[4];
#pragma unroll
            for (int i = 0; i < 4; i++) ra[i] = As[k][ty * 4 + i];
#pragma unroll
            for (int j = 0; j < 4; j++) rb[j] = Bs[k][tx * 4 + j];
#pragma unroll
            for (int i = 0; i < 4; i++)
#pragma unroll
                for (int j = 0; j < 4; j++)
                    acc[i][j] += ra[i] * rb[j];
        }
        __syncthreads();
    }

#pragma unroll
    for (int i = 0; i < 4; i++) {
        int row = bm + ty * 4 + i;
#pragma unroll
        for (int j = 0; j < 4; j++) {
            int col = bn + tx * 4 + j;
            float v = acc[i][j] + bias[col];
            if (epi == EPI_RES) {
                v += res[(size_t)row * N + col];
            } else if (epi == EPI_GELU) {
                float h = v;
                v = 0.5f * h * (1.0f + tanhf(0.7978845608028654f *
                                             (h + 0.044715f * h * h * h)));
            }
            C[(size_t)row * N + col] = v;
        }
    }
}

// ---------------- Windowed attention ---------------------------------------
// grid.x = B*NWH*NWW windows (512), grid.y = head (16), 64 threads = queries.
// Shift (-4,-4) folded into indexing; merge+roll(+4) cancel -> write to src tok.
__global__ __launch_bounds__(64) void attn_kernel(
    const float* __restrict__ q, const float* __restrict__ kv,
    const float* __restrict__ table, float* __restrict__ out)
{
    __shared__ float Ks[64][DK];
    __shared__ float Vs[64][DK];
    __shared__ float tbl[TBL];
    __shared__ int   cnts[64];

    int w    = blockIdx.x;
    int head = blockIdx.y;
    int b  = w >> 6;
    int wi = w & 63;
    int wh = wi >> 3, wwc = wi & 7;
    int e  = threadIdx.x;
    int r  = e >> 3, c = e & 7;

    int gh = (wh * 8 + r + SHIFT) & 63;
    int gw = (wwc * 8 + c + SHIFT) & 63;
    int tok = (b * 64 + gh) * 64 + gw;

    const float* qp = q  + (size_t)tok * DIM      + head * DK;
    const float* kp = kv + (size_t)tok * (2*DIM)  + head * DK;

    float qreg[DK];
#pragma unroll
    for (int d = 0; d < DK; d++) {
        qreg[d]  = qp[d];
        Ks[e][d] = kp[d];
        Vs[e][d] = kp[DIM + d];
    }
    // region id for the mask (computed on unshifted image coords, per ref)
    int ii = wh * 8 + r, jj = wwc * 8 + c;
    int ridi = (ii < HH - WS) ? 0 : ((ii < HH - SHIFT) ? 1 : 2);
    int ridj = (jj < WW_ - WS) ? 0 : ((jj < WW_ - SHIFT) ? 1 : 2);
    cnts[e] = ridi * 3 + ridj;
    for (int t = e; t < TBL; t += 64) tbl[t] = table[t * NHEAD + head];
    __syncthreads();

    const float SCALE = 0.17677669529663687f;  // 1/sqrt(32)
    float s[64];
    float mx = -1e30f;
    int mycnt = cnts[e];
#pragma unroll 4
    for (int kk = 0; kk < 64; kk++) {
        float acc = 0.f;
#pragma unroll
        for (int d = 0; d < DK; d++) acc += qreg[d] * Ks[kk][d];
        int kr = kk >> 3, kc = kk & 7;
        acc = acc * SCALE + tbl[(r - kr + 7) * 15 + (c - kc + 7)];
        if (mycnt != cnts[kk]) acc = -1e9f;
        s[kk] = acc;
        mx = fmaxf(mx, acc);
    }
    float sum = 0.f;
#pragma unroll 4
    for (int kk = 0; kk < 64; kk++) { s[kk] = expf(s[kk] - mx); sum += s[kk]; }
    float inv = 1.f / sum;

    float o[DK];
#pragma unroll
    for (int d = 0; d < DK; d++) o[d] = 0.f;
#pragma unroll 4
    for (int kk = 0; kk < 64; kk++) {
        float p = s[kk];
#pragma unroll
        for (int d = 0; d < DK; d++) o[d] += p * Vs[kk][d];
    }
    float* op = out + (size_t)tok * DIM + head * DK;
#pragma unroll
    for (int d = 0; d < DK; d++) op[d] = o[d] * inv;
}

// ---------------- launch ----------------------------------------------------
extern "C" void kernel_launch(void* const* d_in, const int* in_sizes, int n_in,
                              void* d_out, int out_size)
{
    const float* x_in  = (const float*)d_in[0];
    // d_in[1] = mask (bool)  — recomputed inline
    // d_in[2] = rel_index    — recomputed inline
    const float* Wq   = (const float*)d_in[3];
    const float* bq   = (const float*)d_in[4];
    const float* Wkv  = (const float*)d_in[5];
    const float* bkv  = (const float*)d_in[6];
    const float* Wo   = (const float*)d_in[7];
    const float* bo   = (const float*)d_in[8];
    const float* rtab = (const float*)d_in[9];
    const float* ln1g = (const float*)d_in[10];
    const float* ln1b = (const float*)d_in[11];
    const float* ln2g = (const float*)d_in[12];
    const float* ln2b = (const float*)d_in[13];
    const float* W1   = (const float*)d_in[14];
    const float* b1   = (const float*)d_in[15];
    const float* W2   = (const float*)d_in[16];
    const float* b2   = (const float*)d_in[17];

    float *gx, *gxn, *gq, *gkv, *gat, *gh;
    cudaGetSymbolAddress((void**)&gx,  g_x);
    cudaGetSymbolAddress((void**)&gxn, g_xn);
    cudaGetSymbolAddress((void**)&gq,  g_q);
    cudaGetSymbolAddress((void**)&gkv, g_kv);
    cudaGetSymbolAddress((void**)&gat, g_at);
    cudaGetSymbolAddress((void**)&gh,  g_h);

    cudaMemcpyAsync(gx, x_in, (size_t)NTOK * DIM * sizeof(float),
                    cudaMemcpyDeviceToDevice);

    dim3 gemm_threads(256);
    for (int i = 0; i < LAYERS; i++) {
        const float* Wq_i  = Wq  + (size_t)i * DIM * DIM;
        const float* Wkv_i = Wkv + (size_t)i * DIM * 2 * DIM;
        const float* Wo_i  = Wo  + (size_t)i * DIM * DIM;
        const float* W1_i  = W1  + (size_t)i * DIM * 4 * DIM;
        const float* W2_i  = W2  + (size_t)i * 4 * DIM * DIM;

        // LN1
        ln_kernel<<<NTOK, 128>>>(gx, ln1g + i * DIM, ln1b + i * DIM, gxn);
        // Q = xn @ Wq + bq
        gemm_kernel<<<dim3(DIM / GBN, NTOK / GBM), gemm_threads>>>(
            gxn, Wq_i, bq + i * DIM, nullptr, gq, NTOK, DIM, DIM, EPI_BIAS);
        // KV = xn @ Wkv + bkv
        gemm_kernel<<<dim3(2 * DIM / GBN, NTOK / GBM), gemm_threads>>>(
            gxn, Wkv_i, bkv + i * 2 * DIM, nullptr, gkv, NTOK, 2 * DIM, DIM, EPI_BIAS);
        // windowed attention
        attn_kernel<<<dim3(BATCH * 64, NHEAD), 64>>>(
            gq, gkv, rtab + (size_t)i * TBL * NHEAD, gat);
        // x = x + attn @ Wo + bo
        gemm_kernel<<<dim3(DIM / GBN, NTOK / GBM), gemm_threads>>>(
            gat, Wo_i, bo + i * DIM, gx, gx, NTOK, DIM, DIM, EPI_RES);
        // LN2
        ln_kernel<<<NTOK, 128>>>(gx, ln2g + i * DIM, ln2b + i * DIM, gxn);
        // h = gelu(xn @ W1 + b1)
        gemm_kernel<<<dim3(4 * DIM / GBN, NTOK / GBM), gemm_threads>>>(
            gxn, W1_i, b1 + i * 4 * DIM, nullptr, gh, NTOK, 4 * DIM, DIM, EPI_GELU);
        // x = x + h @ W2 + b2
        gemm_kernel<<<dim3(DIM / GBN, NTOK / GBM), gemm_threads>>>(
            gh, W2_i, b2 + i * DIM, gx, gx, NTOK, DIM, 4 * DIM, EPI_RES);
    }

    cudaMemcpyAsync(d_out, gx, (size_t)NTOK * DIM * sizeof(float),
                    cudaMemcpyDeviceToDevice);
}

// round 6
// speedup vs baseline: 4.3846x; 4.3846x over previous
#include <cuda_runtime.h>
#include <cuda_bf16.h>
#include <math.h>
#include <stdint.h>

// Problem constants
#define BATCH   8
#define HH      64
#define WW_     64
#define DIM     512
#define NHEAD   16
#define DK      32
#define WS      8
#define SHIFT   4
#define LAYERS  4
#define NTOK    (BATCH * HH * WW_)          // 32768
#define TBL     225                          // (2*WS-1)^2

// ---------------- scratch (device globals; no allocation allowed) ----------
__device__ float g_x  [NTOK * DIM];          // running state (f32)
__device__ float g_xn [NTOK * DIM];          // layernorm out (tf32-rounded)
__device__ float g_q  [NTOK * DIM];          // Q (f32)
__device__ float g_kv [NTOK * 2 * DIM];      // K|V (f32)
__device__ float g_at [NTOK * DIM];          // attn out (tf32-rounded)
__device__ float g_h  [NTOK * 4 * DIM];      // MLP hidden (tf32-rounded)
// transposed tf32-rounded weights, [N, K] row-major
__device__ float g_wqT [LAYERS * DIM * DIM];
__device__ float g_wkvT[LAYERS * 2 * DIM * DIM];
__device__ float g_woT [LAYERS * DIM * DIM];
__device__ float g_w1T [LAYERS * 4 * DIM * DIM];
__device__ float g_w2T [LAYERS * DIM * 4 * DIM];

// ---------------- helpers ----------------------------------------------------
__device__ __forceinline__ float rna_tf32(float x) {
    float r; asm("cvt.rna.tf32.f32 %0, %1;" : "=f"(r) : "f"(x)); return r;
}
__device__ __forceinline__ uint32_t smem_u32(const void* p) {
    uint32_t a;
    asm("{ .reg .u64 t; cvta.to.shared.u64 t, %1; cvt.u32.u64 %0, t; }"
        : "=r"(a) : "l"(p));
    return a;
}

// m16n8k8 tf32 MMA (Ampere-class, valid on base sm_103 target)
__device__ __forceinline__ void mma_tf32(
    float* c, const uint32_t* a, uint32_t b0, uint32_t b1)
{
    asm volatile(
        "mma.sync.aligned.m16n8k8.row.col.f32.tf32.tf32.f32 "
        "{%0,%1,%2,%3}, {%4,%5,%6,%7}, {%8,%9}, {%0,%1,%2,%3};\n"
        : "+f"(c[0]), "+f"(c[1]), "+f"(c[2]), "+f"(c[3])
        : "r"(a[0]), "r"(a[1]), "r"(a[2]), "r"(a[3]), "r"(b0), "r"(b1));
}

// ---------------- weight transpose + tf32 rounding --------------------------
// in: W [K, N] f32 row-major -> out: Wt [N, K] tf32-rounded
__global__ __launch_bounds__(256) void wt_prep(
    const float* __restrict__ W, float* __restrict__ Wt, int K, int N)
{
    __shared__ float t[32][33];
    int n0 = blockIdx.x * 32, k0 = blockIdx.y * 32;
    int tx = threadIdx.x, ty = threadIdx.y;   // 32 x 8
#pragma unroll
    for (int i = 0; i < 4; i++)
        t[ty + i * 8][tx] = W[(size_t)(k0 + ty + i * 8) * N + n0 + tx];
    __syncthreads();
#pragma unroll
    for (int i = 0; i < 4; i++)
        Wt[(size_t)(n0 + ty + i * 8) * K + k0 + tx] = rna_tf32(t[tx][ty + i * 8]);
}

// ---------------- LayerNorm (tf32-rounded output) ---------------------------
__global__ __launch_bounds__(128) void ln_kernel(
    const float* __restrict__ x, const float* __restrict__ g,
    const float* __restrict__ b, float* __restrict__ y)
{
    int tok = blockIdx.x;
    const float* xp = x + (size_t)tok * DIM;
    float*       yp = y + (size_t)tok * DIM;
    int tid = threadIdx.x;

    float v[4];
    float s = 0.f;
#pragma unroll
    for (int i = 0; i < 4; i++) { v[i] = xp[tid + i * 128]; s += v[i]; }

    __shared__ float red1[4], red2[4];
#pragma unroll
    for (int o = 16; o > 0; o >>= 1) s += __shfl_xor_sync(0xffffffffu, s, o);
    if ((tid & 31) == 0) red1[tid >> 5] = s;
    __syncthreads();
    float mean = (red1[0] + red1[1] + red1[2] + red1[3]) * (1.f / DIM);

    float s2 = 0.f;
#pragma unroll
    for (int i = 0; i < 4; i++) { float d = v[i] - mean; s2 += d * d; }
#pragma unroll
    for (int o = 16; o > 0; o >>= 1) s2 += __shfl_xor_sync(0xffffffffu, s2, o);
    if ((tid & 31) == 0) red2[tid >> 5] = s2;
    __syncthreads();
    float var  = (red2[0] + red2[1] + red2[2] + red2[3]) * (1.f / DIM);
    float rstd = rsqrtf(var + 1e-5f);

#pragma unroll
    for (int i = 0; i < 4; i++) {
        int c = tid + i * 128;
        yp[c] = rna_tf32((v[i] - mean) * rstd * g[c] + b[c]);
    }
}

// ---------------- tensor-core tf32 GEMM -------------------------------------
// C[M,N] = A[M,K] @ Wt[N,K]^T + bias, epilogue: res-add or gelu.
// CTA 128x128, BK=32, cp.async double buffer, mma.sync m16n8k8 tf32.
#define EPI_BIAS 0
#define EPI_RES  1
#define EPI_GELU 2

#define AST   36                              // smem row stride (floats)
#define TILEB (128 * AST * 4)                 // 18432 bytes per tile
#define GEMM_SMEM (4 * TILEB)                 // 73728 bytes

__device__ __forceinline__ void cpasync_tile(
    uint32_t sm_base, const float* __restrict__ g, int ld,
    int row0, int k0, int tid)
{
#pragma unroll
    for (int i = 0; i < 4; i++) {
        int idx = tid + i * 256;
        int r = idx >> 3, c4 = idx & 7;
        uint32_t saddr = sm_base + (uint32_t)(r * AST + c4 * 4) * 4u;
        const float* gp = g + (size_t)(row0 + r) * ld + k0 + c4 * 4;
        asm volatile("cp.async.cg.shared.global [%0], [%1], 16;\n"
                     :: "r"(saddr), "l"(gp));
    }
}

__global__ __launch_bounds__(256, 2) void gemm_tc(
    const float* __restrict__ A, const float* __restrict__ Wt,
    const float* __restrict__ bias, const float* __restrict__ res,
    float* __restrict__ outF, int N, int K, int epi)
{
    extern __shared__ char smem[];
    float* sA = reinterpret_cast<float*>(smem);              // [2][128*AST]
    float* sB = reinterpret_cast<float*>(smem + 2 * TILEB);  // [2][128*AST]
    uint32_t sAu = smem_u32(sA);
    uint32_t sBu = smem_u32(sB);

    int tid = threadIdx.x;
    int wid = tid >> 5, lane = tid & 31;
    int gq = lane >> 2, tq = lane & 3;        // quad row / quad col
    int wm = wid >> 1, wn = wid & 1;          // warp 32-row block, 64-col block
    int bn = blockIdx.x * 128, bm = blockIdx.y * 128;

    float acc[2][8][4];
#pragma unroll
    for (int mt = 0; mt < 2; mt++)
#pragma unroll
        for (int nt = 0; nt < 8; nt++)
#pragma unroll
            for (int r = 0; r < 4; r++) acc[mt][nt][r] = 0.f;

    const int NKB = K >> 5;

    cpasync_tile(sAu, A,  K, bm, 0, tid);
    cpasync_tile(sBu, Wt, K, bn, 0, tid);
    asm volatile("cp.async.commit_group;");

    for (int kb = 0; kb < NKB; kb++) {
        if (kb + 1 < NKB) {
            int nb = (kb + 1) & 1;
            cpasync_tile(sAu + nb * TILEB, A,  K, bm, (kb + 1) * 32, tid);
            cpasync_tile(sBu + nb * TILEB, Wt, K, bn, (kb + 1) * 32, tid);
            asm volatile("cp.async.commit_group;");
            asm volatile("cp.async.wait_group 1;");
        } else {
            asm volatile("cp.async.wait_group 0;");
        }
        __syncthreads();

        const float* tA = sA + (kb & 1) * (128 * AST) + (wm * 32) * AST;
        const float* tB = sB + (kb & 1) * (128 * AST) + (wn * 64) * AST;
#pragma unroll
        for (int ks = 0; ks < 4; ks++) {
            int kc = ks * 8;
            uint32_t afr[2][4];
#pragma unroll
            for (int mt = 0; mt < 2; mt++) {
                const float* ap = tA + mt * 16 * AST;
                afr[mt][0] = __float_as_uint(ap[(gq    ) * AST + kc + tq    ]);
                afr[mt][1] = __float_as_uint(ap[(gq + 8) * AST + kc + tq    ]);
                afr[mt][2] = __float_as_uint(ap[(gq    ) * AST + kc + tq + 4]);
                afr[mt][3] = __float_as_uint(ap[(gq + 8) * AST + kc + tq + 4]);
            }
#pragma unroll
            for (int nt = 0; nt < 8; nt++) {
                const float* bp = tB + (nt * 8 + gq) * AST + kc;
                uint32_t b0 = __float_as_uint(bp[tq    ]);
                uint32_t b1 = __float_as_uint(bp[tq + 4]);
                mma_tf32(acc[0][nt], afr[0], b0, b1);
                mma_tf32(acc[1][nt], afr[1], b0, b1);
            }
        }
        __syncthreads();
    }

    // ---- epilogue: straight from registers, float2 stores -----------------
#pragma unroll
    for (int mt = 0; mt < 2; mt++) {
        int row0 = bm + wm * 32 + mt * 16 + gq;
        int row1 = row0 + 8;
#pragma unroll
        for (int nt = 0; nt < 8; nt++) {
            int col = bn + wn * 64 + nt * 8 + 2 * tq;
            float2 bc = *reinterpret_cast<const float2*>(bias + col);
            float v00 = acc[mt][nt][0] + bc.x;
            float v01 = acc[mt][nt][1] + bc.y;
            float v10 = acc[mt][nt][2] + bc.x;
            float v11 = acc[mt][nt][3] + bc.y;
            if (epi == EPI_RES) {
                float2 r0 = *reinterpret_cast<const float2*>(
                    res + (size_t)row0 * N + col);
                float2 r1 = *reinterpret_cast<const float2*>(
                    res + (size_t)row1 * N + col);
                v00 += r0.x; v01 += r0.y; v10 += r1.x; v11 += r1.y;
            } else if (epi == EPI_GELU) {
                const float K0 = 0.7978845608028654f, K1 = 0.044715f;
                v00 = rna_tf32(0.5f * v00 * (1.f + tanhf(K0 * (v00 + K1 * v00 * v00 * v00))));
                v01 = rna_tf32(0.5f * v01 * (1.f + tanhf(K0 * (v01 + K1 * v01 * v01 * v01))));
                v10 = rna_tf32(0.5f * v10 * (1.f + tanhf(K0 * (v10 + K1 * v10 * v10 * v10))));
                v11 = rna_tf32(0.5f * v11 * (1.f + tanhf(K0 * (v11 + K1 * v11 * v11 * v11))));
            }
            *reinterpret_cast<float2*>(outF + (size_t)row0 * N + col) =
                make_float2(v00, v01);
            *reinterpret_cast<float2*>(outF + (size_t)row1 * N + col) =
                make_float2(v10, v11);
        }
    }
}

// ---------------- Windowed attention ----------------------------------------
__global__ __launch_bounds__(64) void attn_kernel(
    const float* __restrict__ q, const float* __restrict__ kv,
    const float* __restrict__ table, float* __restrict__ out)
{
    __shared__ float Ks[64][DK];
    __shared__ float Vs[64][DK];
    __shared__ float tbl[TBL];
    __shared__ int   cnts[64];

    int w    = blockIdx.x;
    int head = blockIdx.y;
    int b  = w >> 6;
    int wi = w & 63;
    int wh = wi >> 3, wwc = wi & 7;
    int e  = threadIdx.x;
    int r  = e >> 3, c = e & 7;

    int gh = (wh * 8 + r + SHIFT) & 63;
    int gw = (wwc * 8 + c + SHIFT) & 63;
    int tok = (b * 64 + gh) * 64 + gw;

    const float* qp = q  + (size_t)tok * DIM      + head * DK;
    const float* kp = kv + (size_t)tok * (2*DIM)  + head * DK;

    float qreg[DK];
#pragma unroll
    for (int d = 0; d < DK; d++) {
        qreg[d]  = qp[d];
        Ks[e][d] = kp[d];
        Vs[e][d] = kp[DIM + d];
    }
    int ii = wh * 8 + r, jj = wwc * 8 + c;
    int ridi = (ii < HH - WS) ? 0 : ((ii < HH - SHIFT) ? 1 : 2);
    int ridj = (jj < WW_ - WS) ? 0 : ((jj < WW_ - SHIFT) ? 1 : 2);
    cnts[e] = ridi * 3 + ridj;
    for (int t = e; t < TBL; t += 64) tbl[t] = table[t * NHEAD + head];
    __syncthreads();

    const float SCALE = 0.17677669529663687f;  // 1/sqrt(32)
    float s[64];
    float mx = -1e30f;
    int mycnt = cnts[e];
#pragma unroll 4
    for (int kk = 0; kk < 64; kk++) {
        float acc = 0.f;
#pragma unroll
        for (int d = 0; d < DK; d++) acc += qreg[d] * Ks[kk][d];
        int kr = kk >> 3, kc = kk & 7;
        acc = acc * SCALE + tbl[(r - kr + 7) * 15 + (c - kc + 7)];
        if (mycnt != cnts[kk]) acc = -1e9f;
        s[kk] = acc;
        mx = fmaxf(mx, acc);
    }
    float sum = 0.f;
#pragma unroll 4
    for (int kk = 0; kk < 64; kk++) { s[kk] = expf(s[kk] - mx); sum += s[kk]; }
    float inv = 1.f / sum;

    float o[DK];
#pragma unroll
    for (int d = 0; d < DK; d++) o[d] = 0.f;
#pragma unroll 4
    for (int kk = 0; kk < 64; kk++) {
        float p = s[kk];
#pragma unroll
        for (int d = 0; d < DK; d++) o[d] += p * Vs[kk][d];
    }
    float* op = out + (size_t)tok * DIM + head * DK;
#pragma unroll
    for (int d = 0; d < DK; d++) op[d] = rna_tf32(o[d] * inv);
}

// ---------------- launch ----------------------------------------------------
extern "C" void kernel_launch(void* const* d_in, const int* in_sizes, int n_in,
                              void* d_out, int out_size)
{
    const float* x_in  = (const float*)d_in[0];
    const float* Wq   = (const float*)d_in[3];
    const float* bq   = (const float*)d_in[4];
    const float* Wkv  = (const float*)d_in[5];
    const float* bkv  = (const float*)d_in[6];
    const float* Wo   = (const float*)d_in[7];
    const float* bo   = (const float*)d_in[8];
    const float* rtab = (const float*)d_in[9];
    const float* ln1g = (const float*)d_in[10];
    const float* ln1b = (const float*)d_in[11];
    const float* ln2g = (const float*)d_in[12];
    const float* ln2b = (const float*)d_in[13];
    const float* W1   = (const float*)d_in[14];
    const float* b1   = (const float*)d_in[15];
    const float* W2   = (const float*)d_in[16];
    const float* b2   = (const float*)d_in[17];

    float *gx, *gxn, *gqp, *gkv, *gat, *ghid;
    float *wqT, *wkvT, *woT, *w1T, *w2T;
    cudaGetSymbolAddress((void**)&gx,   g_x);
    cudaGetSymbolAddress((void**)&gxn,  g_xn);
    cudaGetSymbolAddress((void**)&gqp,  g_q);
    cudaGetSymbolAddress((void**)&gkv,  g_kv);
    cudaGetSymbolAddress((void**)&gat,  g_at);
    cudaGetSymbolAddress((void**)&ghid, g_h);
    cudaGetSymbolAddress((void**)&wqT,  g_wqT);
    cudaGetSymbolAddress((void**)&wkvT, g_wkvT);
    cudaGetSymbolAddress((void**)&woT,  g_woT);
    cudaGetSymbolAddress((void**)&w1T,  g_w1T);
    cudaGetSymbolAddress((void**)&w2T,  g_w2T);

    cudaFuncSetAttribute(gemm_tc,
        cudaFuncAttributeMaxDynamicSharedMemorySize, GEMM_SMEM);

    cudaMemcpyAsync(gx, x_in, (size_t)NTOK * DIM * sizeof(float),
                    cudaMemcpyDeviceToDevice);

    // weight transposes (tf32-rounded)
    dim3 tb(32, 8);
    for (int i = 0; i < LAYERS; i++) {
        wt_prep<<<dim3(16, 16), tb>>>(Wq  + (size_t)i*DIM*DIM,    wqT  + (size_t)i*DIM*DIM,    DIM,   DIM);
        wt_prep<<<dim3(32, 16), tb>>>(Wkv + (size_t)i*DIM*2*DIM,  wkvT + (size_t)i*2*DIM*DIM,  DIM,   2*DIM);
        wt_prep<<<dim3(16, 16), tb>>>(Wo  + (size_t)i*DIM*DIM,    woT  + (size_t)i*DIM*DIM,    DIM,   DIM);
        wt_prep<<<dim3(64, 16), tb>>>(W1  + (size_t)i*DIM*4*DIM,  w1T  + (size_t)i*4*DIM*DIM,  DIM,   4*DIM);
        wt_prep<<<dim3(16, 64), tb>>>(W2  + (size_t)i*4*DIM*DIM,  w2T  + (size_t)i*DIM*4*DIM,  4*DIM, DIM);
    }

    for (int i = 0; i < LAYERS; i++) {
        // LN1
        ln_kernel<<<NTOK, 128>>>(gx, ln1g + i * DIM, ln1b + i * DIM, gxn);
        // Q = xn @ Wq + bq
        gemm_tc<<<dim3(DIM/128, NTOK/128), 256, GEMM_SMEM>>>(
            gxn, wqT + (size_t)i*DIM*DIM, bq + i*DIM, nullptr, gqp,
            DIM, DIM, EPI_BIAS);
        // KV = xn @ Wkv + bkv
        gemm_tc<<<dim3(2*DIM/128, NTOK/128), 256, GEMM_SMEM>>>(
            gxn, wkvT + (size_t)i*2*DIM*DIM, bkv + i*2*DIM, nullptr, gkv,
            2*DIM, DIM, EPI_BIAS);
        // windowed attention
        attn_kernel<<<dim3(BATCH * 64, NHEAD), 64>>>(
            gqp, gkv, rtab + (size_t)i * TBL * NHEAD, gat);
        // x = x + attn @ Wo + bo
        gemm_tc<<<dim3(DIM/128, NTOK/128), 256, GEMM_SMEM>>>(
            gat, woT + (size_t)i*DIM*DIM, bo + i*DIM, gx, gx,
            DIM, DIM, EPI_RES);
        // LN2
        ln_kernel<<<NTOK, 128>>>(gx, ln2g + i * DIM, ln2b + i * DIM, gxn);
        // h = gelu(xn @ W1 + b1)
        gemm_tc<<<dim3(4*DIM/128, NTOK/128), 256, GEMM_SMEM>>>(
            gxn, w1T + (size_t)i*4*DIM*DIM, b1 + i*4*DIM, nullptr, ghid,
            4*DIM, DIM, EPI_GELU);
        // x = x + h @ W2 + b2
        gemm_tc<<<dim3(DIM/128, NTOK/128), 256, GEMM_SMEM>>>(
            ghid, w2T + (size_t)i*DIM*4*DIM, b2 + i*DIM, gx, gx,
            DIM, 4*DIM, EPI_RES);
    }

    cudaMemcpyAsync(d_out, gx, (size_t)NTOK * DIM * sizeof(float),
                    cudaMemcpyDeviceToDevice);
}

// round 8
// speedup vs baseline: 6.0996x; 1.3911x over previous
#include <cuda_runtime.h>
#include <cuda_fp16.h>
#include <math.h>
#include <stdint.h>

// Problem constants
#define BATCH   8
#define HH      64
#define WW_     64
#define DIM     512
#define NHEAD   16
#define DK      32
#define WS      8
#define SHIFT   4
#define LAYERS  4
#define NTOK    (BATCH * HH * WW_)          // 32768
#define TBL     225                          // (2*WS-1)^2

// ---------------- scratch (device globals; no allocation allowed) ----------
__device__ float  g_x  [NTOK * DIM];         // running state (f32)
__device__ __half g_xn [NTOK * DIM];         // layernorm out (fp16)
__device__ __half g_q  [NTOK * DIM];         // Q (fp16)
__device__ __half g_kv [NTOK * 2 * DIM];     // K|V (fp16)
__device__ __half g_at [NTOK * DIM];         // attn out (fp16)
__device__ __half g_h  [NTOK * 4 * DIM];     // MLP hidden (fp16)
// transposed fp16 weights, [N, K] row-major
__device__ __half g_wqT [LAYERS * DIM * DIM];
__device__ __half g_wkvT[LAYERS * 2 * DIM * DIM];
__device__ __half g_woT [LAYERS * DIM * DIM];
__device__ __half g_w1T [LAYERS * 4 * DIM * DIM];
__device__ __half g_w2T [LAYERS * DIM * 4 * DIM];

// ---------------- helpers ----------------------------------------------------
__device__ __forceinline__ uint32_t smem_u32(const void* p) {
    uint32_t a;
    asm("{ .reg .u64 t; cvta.to.shared.u64 t, %1; cvt.u32.u64 %0, t; }"
        : "=r"(a) : "l"(p));
    return a;
}

// m16n8k16 fp16 MMA, fp32 accumulate (Ampere-class, base ISA)
__device__ __forceinline__ void mma_f16(
    float* c, const uint32_t* a, uint32_t b0, uint32_t b1)
{
    asm volatile(
        "mma.sync.aligned.m16n8k16.row.col.f32.f16.f16.f32 "
        "{%0,%1,%2,%3}, {%4,%5,%6,%7}, {%8,%9}, {%0,%1,%2,%3};\n"
        : "+f"(c[0]), "+f"(c[1]), "+f"(c[2]), "+f"(c[3])
        : "r"(a[0]), "r"(a[1]), "r"(a[2]), "r"(a[3]), "r"(b0), "r"(b1));
}

__device__ __forceinline__ void ldmx4(uint32_t* r, uint32_t addr) {
    asm volatile(
        "ldmatrix.sync.aligned.m8n8.x4.shared.b16 {%0,%1,%2,%3}, [%4];"
        : "=r"(r[0]), "=r"(r[1]), "=r"(r[2]), "=r"(r[3]) : "r"(addr));
}

// ---------------- weight transpose + fp16 convert ----------------------------
// in: W [K, N] f32 row-major -> out: Wt [N, K] fp16
__global__ __launch_bounds__(256) void wt_prep(
    const float* __restrict__ W, __half* __restrict__ Wt, int K, int N)
{
    __shared__ float t[32][33];
    int n0 = blockIdx.x * 32, k0 = blockIdx.y * 32;
    int tx = threadIdx.x, ty = threadIdx.y;   // 32 x 8
#pragma unroll
    for (int i = 0; i < 4; i++)
        t[ty + i * 8][tx] = W[(size_t)(k0 + ty + i * 8) * N + n0 + tx];
    __syncthreads();
#pragma unroll
    for (int i = 0; i < 4; i++)
        Wt[(size_t)(n0 + ty + i * 8) * K + k0 + tx] =
            __float2half_rn(t[tx][ty + i * 8]);
}

// ---------------- LayerNorm (fp16 output) ------------------------------------
__global__ __launch_bounds__(128) void ln_kernel(
    const float* __restrict__ x, const float* __restrict__ g,
    const float* __restrict__ b, __half* __restrict__ y)
{
    int tok = blockIdx.x;
    const float4* xp = reinterpret_cast<const float4*>(x + (size_t)tok * DIM);
    int tid = threadIdx.x;

    float4 v = xp[tid];
    float s = v.x + v.y + v.z + v.w;

    __shared__ float red1[4], red2[4];
#pragma unroll
    for (int o = 16; o > 0; o >>= 1) s += __shfl_xor_sync(0xffffffffu, s, o);
    if ((tid & 31) == 0) red1[tid >> 5] = s;
    __syncthreads();
    float mean = (red1[0] + red1[1] + red1[2] + red1[3]) * (1.f / DIM);

    float dx = v.x - mean, dy = v.y - mean, dz = v.z - mean, dw = v.w - mean;
    float s2 = dx * dx + dy * dy + dz * dz + dw * dw;
#pragma unroll
    for (int o = 16; o > 0; o >>= 1) s2 += __shfl_xor_sync(0xffffffffu, s2, o);
    if ((tid & 31) == 0) red2[tid >> 5] = s2;
    __syncthreads();
    float var  = (red2[0] + red2[1] + red2[2] + red2[3]) * (1.f / DIM);
    float rstd = rsqrtf(var + 1e-5f);

    int c = tid * 4;
    float4 gg = reinterpret_cast<const float4*>(g)[tid];
    float4 bb = reinterpret_cast<const float4*>(b)[tid];
    float r0 = dx * rstd * gg.x + bb.x;
    float r1 = dy * rstd * gg.y + bb.y;
    float r2 = dz * rstd * gg.z + bb.z;
    float r3 = dw * rstd * gg.w + bb.w;
    __half2* yp2 = reinterpret_cast<__half2*>(y + (size_t)tok * DIM + c);
    yp2[0] = __floats2half2_rn(r0, r1);
    yp2[1] = __floats2half2_rn(r2, r3);
}

// ---------------- tensor-core fp16 GEMM --------------------------------------
// C[M,N] = A[M,K] @ Wt[N,K]^T + bias; epi selects res-add(f32 out) / gelu /
// plain bias (fp16 out). CTA 128x128, BK=32, 2-stage cp.async, ldmatrix.
#define EPI_BIAS 0
#define EPI_RES  1
#define EPI_GELU 2

#define RSTH   40                               // smem row stride (halfs)
#define ATILE  (128 * RSTH * 2)                 // 10240 B per operand tile
#define STAGEB (2 * ATILE)                      // 20480 B per stage
#define GEMM_SMEM (2 * STAGEB)                  // 40960 B

__global__ __launch_bounds__(256, 2) void gemm_tc(
    const __half* __restrict__ A, const __half* __restrict__ Wt,
    const float* __restrict__ bias, const float* __restrict__ res,
    void* __restrict__ outP, int N, int K, int epi)
{
    extern __shared__ char smem[];
    uint32_t sbase = smem_u32(smem);

    int tid = threadIdx.x;
    int wid = tid >> 5, lane = tid & 31;
    int gq = lane >> 2, tq = lane & 3;
    int wm = wid >> 1, wn = wid & 1;           // warp: 32 rows x 64 cols
    int bn = blockIdx.x * 128, bm = blockIdx.y * 128;

    // ldmatrix lane offsets (bytes within operand tile)
    int t8 = lane >> 3, l8 = lane & 7;
    // A fragment: m0=rows0-7/k0-7, m1=rows8-15/k0-7, m2=rows0-7/k8-15, m3=rows8-15/k8-15
    uint32_t a_off = (uint32_t)((wm * 32 + (t8 & 1) * 8 + l8) * (RSTH * 2)
                                + (t8 >> 1) * 16);
    // B fragment (non-trans; Wt rows are n): m0=n0-7/k0-7, m1=n0-7/k8-15,
    //                                         m2=n8-15/k0-7, m3=n8-15/k8-15
    uint32_t b_off = (uint32_t)((wn * 64 + (t8 >> 1) * 8 + l8) * (RSTH * 2)
                                + (t8 & 1) * 16);

    float acc[2][8][4];
#pragma unroll
    for (int mt = 0; mt < 2; mt++)
#pragma unroll
        for (int nt = 0; nt < 8; nt++)
#pragma unroll
            for (int r = 0; r < 4; r++) acc[mt][nt][r] = 0.f;

    const int NKB = K >> 5;

    // cp.async loader: tile rows = 128, 64B each (4x16B chunks)
    int c_row0 = tid >> 2, c_c = tid & 3;
    int c_row1 = (tid + 256) >> 2;

#define LOAD_STAGE(kb, stg) do {                                              \
    uint32_t sA = sbase + (stg) * STAGEB;                                     \
    uint32_t sB = sA + ATILE;                                                 \
    const __half* ga0 = A  + (size_t)(bm + c_row0) * K + (kb) * 32 + c_c * 8; \
    const __half* gb0 = Wt + (size_t)(bn + c_row0) * K + (kb) * 32 + c_c * 8; \
    const __half* ga1 = A  + (size_t)(bm + c_row1) * K + (kb) * 32 + c_c * 8; \
    const __half* gb1 = Wt + (size_t)(bn + c_row1) * K + (kb) * 32 + c_c * 8; \
    uint32_t d0 = (uint32_t)(c_row0 * (RSTH * 2) + c_c * 16);                 \
    uint32_t d1 = (uint32_t)(c_row1 * (RSTH * 2) + c_c * 16);                 \
    asm volatile("cp.async.cg.shared.global [%0], [%1], 16;" :: "r"(sA + d0), "l"(ga0)); \
    asm volatile("cp.async.cg.shared.global [%0], [%1], 16;" :: "r"(sB + d0), "l"(gb0)); \
    asm volatile("cp.async.cg.shared.global [%0], [%1], 16;" :: "r"(sA + d1), "l"(ga1)); \
    asm volatile("cp.async.cg.shared.global [%0], [%1], 16;" :: "r"(sB + d1), "l"(gb1)); \
} while (0)

    LOAD_STAGE(0, 0);
    asm volatile("cp.async.commit_group;");

    for (int kb = 0; kb < NKB; kb++) {
        asm volatile("cp.async.wait_group 0;");
        __syncthreads();
        if (kb + 1 < NKB) {
            LOAD_STAGE(kb + 1, (kb + 1) & 1);
            asm volatile("cp.async.commit_group;");
        }
        uint32_t sA = sbase + (kb & 1) * STAGEB;
        uint32_t sB = sA + ATILE;
#pragma unroll
        for (int ks = 0; ks < 2; ks++) {
            uint32_t af[2][4];
            ldmx4(af[0], sA + a_off + ks * 32);
            ldmx4(af[1], sA + a_off + ks * 32 + 16 * (RSTH * 2));
            uint32_t bf[4][4];
#pragma unroll
            for (int p = 0; p < 4; p++)
                ldmx4(bf[p], sB + b_off + ks * 32 + p * 16 * (RSTH * 2));
#pragma unroll
            for (int p = 0; p < 4; p++) {
                // regs: 0 = n(+0..7) k0-7 (b0), 1 = n(+0..7) k8-15 (b1),
                //       2 = n(+8..15) k0-7,    3 = n(+8..15) k8-15
                mma_f16(acc[0][2 * p],     af[0], bf[p][0], bf[p][1]);
                mma_f16(acc[1][2 * p],     af[1], bf[p][0], bf[p][1]);
                mma_f16(acc[0][2 * p + 1], af[0], bf[p][2], bf[p][3]);
                mma_f16(acc[1][2 * p + 1], af[1], bf[p][2], bf[p][3]);
            }
        }
        __syncthreads();
    }

    // ---- epilogue ----------------------------------------------------------
    float*  outF = reinterpret_cast<float*>(outP);
    __half* outH = reinterpret_cast<__half*>(outP);
#pragma unroll
    for (int mt = 0; mt < 2; mt++) {
        int row0 = bm + wm * 32 + mt * 16 + gq;
        int row1 = row0 + 8;
#pragma unroll
        for (int nt = 0; nt < 8; nt++) {
            int col = bn + wn * 64 + nt * 8 + 2 * tq;
            float2 bc = *reinterpret_cast<const float2*>(bias + col);
            float v00 = acc[mt][nt][0] + bc.x;
            float v01 = acc[mt][nt][1] + bc.y;
            float v10 = acc[mt][nt][2] + bc.x;
            float v11 = acc[mt][nt][3] + bc.y;
            if (epi == EPI_RES) {
                float2 r0 = *reinterpret_cast<const float2*>(
                    res + (size_t)row0 * N + col);
                float2 r1 = *reinterpret_cast<const float2*>(
                    res + (size_t)row1 * N + col);
                *reinterpret_cast<float2*>(outF + (size_t)row0 * N + col) =
                    make_float2(v00 + r0.x, v01 + r0.y);
                *reinterpret_cast<float2*>(outF + (size_t)row1 * N + col) =
                    make_float2(v10 + r1.x, v11 + r1.y);
            } else if (epi == EPI_GELU) {
                const float K0 = 0.7978845608028654f, K1 = 0.044715f;
                v00 = 0.5f * v00 * (1.f + tanhf(K0 * (v00 + K1 * v00 * v00 * v00)));
                v01 = 0.5f * v01 * (1.f + tanhf(K0 * (v01 + K1 * v01 * v01 * v01)));
                v10 = 0.5f * v10 * (1.f + tanhf(K0 * (v10 + K1 * v10 * v10 * v10)));
                v11 = 0.5f * v11 * (1.f + tanhf(K0 * (v11 + K1 * v11 * v11 * v11)));
                *reinterpret_cast<__half2*>(outH + (size_t)row0 * N + col) =
                    __floats2half2_rn(v00, v01);
                *reinterpret_cast<__half2*>(outH + (size_t)row1 * N + col) =
                    __floats2half2_rn(v10, v11);
            } else {
                *reinterpret_cast<__half2*>(outH + (size_t)row0 * N + col) =
                    __floats2half2_rn(v00, v01);
                *reinterpret_cast<__half2*>(outH + (size_t)row1 * N + col) =
                    __floats2half2_rn(v10, v11);
            }
        }
    }
}

// ---------------- Windowed attention (fp16 I/O, f32 math) --------------------
__global__ __launch_bounds__(64) void attn_kernel(
    const __half* __restrict__ q, const __half* __restrict__ kv,
    const float* __restrict__ table, __half* __restrict__ out)
{
    __shared__ float Ks[64][DK];
    __shared__ float Vs[64][DK];
    __shared__ float tbl[TBL];
    __shared__ int   cnts[64];

    int w    = blockIdx.x;
    int head = blockIdx.y;
    int b  = w >> 6;
    int wi = w & 63;
    int wh = wi >> 3, wwc = wi & 7;
    int e  = threadIdx.x;
    int r  = e >> 3, c = e & 7;

    int gh = (wh * 8 + r + SHIFT) & 63;
    int gw = (wwc * 8 + c + SHIFT) & 63;
    int tok = (b * 64 + gh) * 64 + gw;

    const __half* qp = q  + (size_t)tok * DIM      + head * DK;
    const __half* kp = kv + (size_t)tok * (2*DIM)  + head * DK;

    float qreg[DK];
#pragma unroll
    for (int d = 0; d < DK; d++) {
        qreg[d]  = __half2float(qp[d]);
        Ks[e][d] = __half2float(kp[d]);
        Vs[e][d] = __half2float(kp[DIM + d]);
    }
    int ii = wh * 8 + r, jj = wwc * 8 + c;
    int ridi = (ii < HH - WS) ? 0 : ((ii < HH - SHIFT) ? 1 : 2);
    int ridj = (jj < WW_ - WS) ? 0 : ((jj < WW_ - SHIFT) ? 1 : 2);
    cnts[e] = ridi * 3 + ridj;
    for (int t = e; t < TBL; t += 64) tbl[t] = table[t * NHEAD + head];
    __syncthreads();

    const float SCALE = 0.17677669529663687f;  // 1/sqrt(32)
    float s[64];
    float mx = -1e30f;
    int mycnt = cnts[e];
#pragma unroll 4
    for (int kk = 0; kk < 64; kk++) {
        float acc = 0.f;
#pragma unroll
        for (int d = 0; d < DK; d++) acc += qreg[d] * Ks[kk][d];
        int kr = kk >> 3, kc = kk & 7;
        acc = acc * SCALE + tbl[(r - kr + 7) * 15 + (c - kc + 7)];
        if (mycnt != cnts[kk]) acc = -1e9f;
        s[kk] = acc;
        mx = fmaxf(mx, acc);
    }
    float sum = 0.f;
#pragma unroll 4
    for (int kk = 0; kk < 64; kk++) { s[kk] = expf(s[kk] - mx); sum += s[kk]; }
    float inv = 1.f / sum;

    float o[DK];
#pragma unroll
    for (int d = 0; d < DK; d++) o[d] = 0.f;
#pragma unroll 4
    for (int kk = 0; kk < 64; kk++) {
        float p = s[kk];
#pragma unroll
        for (int d = 0; d < DK; d++) o[d] += p * Vs[kk][d];
    }
    __half* op = out + (size_t)tok * DIM + head * DK;
#pragma unroll
    for (int d = 0; d < DK; d++) op[d] = __float2half_rn(o[d] * inv);
}

// ---------------- launch ----------------------------------------------------
extern "C" void kernel_launch(void* const* d_in, const int* in_sizes, int n_in,
                              void* d_out, int out_size)
{
    const float* x_in  = (const float*)d_in[0];
    const float* Wq   = (const float*)d_in[3];
    const float* bq   = (const float*)d_in[4];
    const float* Wkv  = (const float*)d_in[5];
    const float* bkv  = (const float*)d_in[6];
    const float* Wo   = (const float*)d_in[7];
    const float* bo   = (const float*)d_in[8];
    const float* rtab = (const float*)d_in[9];
    const float* ln1g = (const float*)d_in[10];
    const float* ln1b = (const float*)d_in[11];
    const float* ln2g = (const float*)d_in[12];
    const float* ln2b = (const float*)d_in[13];
    const float* W1   = (const float*)d_in[14];
    const float* b1   = (const float*)d_in[15];
    const float* W2   = (const float*)d_in[16];
    const float* b2   = (const float*)d_in[17];

    float *gx;
    __half *gxn, *gqp, *gkv, *gat, *ghid;
    __half *wqT, *wkvT, *woT, *w1T, *w2T;
    cudaGetSymbolAddress((void**)&gx,   g_x);
    cudaGetSymbolAddress((void**)&gxn,  g_xn);
    cudaGetSymbolAddress((void**)&gqp,  g_q);
    cudaGetSymbolAddress((void**)&gkv,  g_kv);
    cudaGetSymbolAddress((void**)&gat,  g_at);
    cudaGetSymbolAddress((void**)&ghid, g_h);
    cudaGetSymbolAddress((void**)&wqT,  g_wqT);
    cudaGetSymbolAddress((void**)&wkvT, g_wkvT);
    cudaGetSymbolAddress((void**)&woT,  g_woT);
    cudaGetSymbolAddress((void**)&w1T,  g_w1T);
    cudaGetSymbolAddress((void**)&w2T,  g_w2T);

    cudaMemcpyAsync(gx, x_in, (size_t)NTOK * DIM * sizeof(float),
                    cudaMemcpyDeviceToDevice);

    // weight transposes (fp16)
    dim3 tb(32, 8);
    for (int i = 0; i < LAYERS; i++) {
        wt_prep<<<dim3(16, 16), tb>>>(Wq  + (size_t)i*DIM*DIM,    wqT  + (size_t)i*DIM*DIM,    DIM,   DIM);
        wt_prep<<<dim3(32, 16), tb>>>(Wkv + (size_t)i*DIM*2*DIM,  wkvT + (size_t)i*2*DIM*DIM,  DIM,   2*DIM);
        wt_prep<<<dim3(16, 16), tb>>>(Wo  + (size_t)i*DIM*DIM,    woT  + (size_t)i*DIM*DIM,    DIM,   DIM);
        wt_prep<<<dim3(64, 16), tb>>>(W1  + (size_t)i*DIM*4*DIM,  w1T  + (size_t)i*4*DIM*DIM,  DIM,   4*DIM);
        wt_prep<<<dim3(16, 64), tb>>>(W2  + (size_t)i*4*DIM*DIM,  w2T  + (size_t)i*DIM*4*DIM,  4*DIM, DIM);
    }

    for (int i = 0; i < LAYERS; i++) {
        // LN1
        ln_kernel<<<NTOK, 128>>>(gx, ln1g + i * DIM, ln1b + i * DIM, gxn);
        // Q = xn @ Wq + bq
        gemm_tc<<<dim3(DIM/128, NTOK/128), 256, GEMM_SMEM>>>(
            gxn, wqT + (size_t)i*DIM*DIM, bq + i*DIM, nullptr, gqp,
            DIM, DIM, EPI_BIAS);
        // KV = xn @ Wkv + bkv
        gemm_tc<<<dim3(2*DIM/128, NTOK/128), 256, GEMM_SMEM>>>(
            gxn, wkvT + (size_t)i*2*DIM*DIM, bkv + i*2*DIM, nullptr, gkv,
            2*DIM, DIM, EPI_BIAS);
        // windowed attention
        attn_kernel<<<dim3(BATCH * 64, NHEAD), 64>>>(
            gqp, gkv, rtab + (size_t)i * TBL * NHEAD, gat);
        // x = x + attn @ Wo + bo
        gemm_tc<<<dim3(DIM/128, NTOK/128), 256, GEMM_SMEM>>>(
            gat, woT + (size_t)i*DIM*DIM, bo + i*DIM, gx, gx,
            DIM, DIM, EPI_RES);
        // LN2
        ln_kernel<<<NTOK, 128>>>(gx, ln2g + i * DIM, ln2b + i * DIM, gxn);
        // h = gelu(xn @ W1 + b1)
        gemm_tc<<<dim3(4*DIM/128, NTOK/128), 256, GEMM_SMEM>>>(
            gxn, w1T + (size_t)i*4*DIM*DIM, b1 + i*4*DIM, nullptr, ghid,
            4*DIM, DIM, EPI_GELU);
        // x = x + h @ W2 + b2
        gemm_tc<<<dim3(DIM/128, NTOK/128), 256, GEMM_SMEM>>>(
            ghid, w2T + (size_t)i*DIM*4*DIM, b2 + i*DIM, gx, gx,
            DIM, 4*DIM, EPI_RES);
    }

    cudaMemcpyAsync(d_out, gx, (size_t)NTOK * DIM * sizeof(float),
                    cudaMemcpyDeviceToDevice);
}

// round 10
// speedup vs baseline: 6.1375x; 1.0062x over previous
#include <cuda_runtime.h>
#include <cuda_fp16.h>
#include <math.h>
#include <stdint.h>

// Problem constants
#define BATCH   8
#define HH      64
#define WW_     64
#define DIM     512
#define NHEAD   16
#define DK      32
#define WS      8
#define SHIFT   4
#define LAYERS  4
#define NTOK    (BATCH * HH * WW_)          // 32768
#define TBL     225                          // (2*WS-1)^2
#define QKVN    (3 * DIM)                    // 1536

// ---------------- scratch (device globals; no allocation allowed) ----------
__device__ float  g_x   [NTOK * DIM];        // running state (f32)
__device__ __half g_xn  [NTOK * DIM];        // layernorm out (fp16)
__device__ __half g_qkv [NTOK * QKVN];       // Q|K|V (fp16)
__device__ __half g_at  [NTOK * DIM];        // attn out (fp16)
__device__ __half g_h   [NTOK * 4 * DIM];    // MLP hidden (fp16)
// transposed fp16 weights, [N, K] row-major
__device__ __half g_wqkvT[LAYERS * QKVN * DIM];   // rows: 0-511 Wq, 512-1535 Wkv
__device__ float  g_bqkv [LAYERS * QKVN];
__device__ __half g_woT [LAYERS * DIM * DIM];
__device__ __half g_w1T [LAYERS * 4 * DIM * DIM];
__device__ __half g_w2T [LAYERS * DIM * 4 * DIM];

// ---------------- helpers ----------------------------------------------------
__device__ __forceinline__ uint32_t smem_u32(const void* p) {
    uint32_t a;
    asm("{ .reg .u64 t; cvta.to.shared.u64 t, %1; cvt.u32.u64 %0, t; }"
        : "=r"(a) : "l"(p));
    return a;
}

__device__ __forceinline__ void mma_f16(
    float* c, const uint32_t* a, uint32_t b0, uint32_t b1)
{
    asm volatile(
        "mma.sync.aligned.m16n8k16.row.col.f32.f16.f16.f32 "
        "{%0,%1,%2,%3}, {%4,%5,%6,%7}, {%8,%9}, {%0,%1,%2,%3};\n"
        : "+f"(c[0]), "+f"(c[1]), "+f"(c[2]), "+f"(c[3])
        : "r"(a[0]), "r"(a[1]), "r"(a[2]), "r"(a[3]), "r"(b0), "r"(b1));
}

__device__ __forceinline__ void ldmx4(uint32_t* r, uint32_t addr) {
    asm volatile(
        "ldmatrix.sync.aligned.m8n8.x4.shared.b16 {%0,%1,%2,%3}, [%4];"
        : "=r"(r[0]), "=r"(r[1]), "=r"(r[2]), "=r"(r[3]) : "r"(addr));
}

// ---------------- weight transpose + fp16 convert ----------------------------
// in: W [K, N] f32 row-major -> out: Wt [N, K] fp16
__global__ __launch_bounds__(256) void wt_prep(
    const float* __restrict__ W, __half* __restrict__ Wt, int K, int N)
{
    __shared__ float t[32][33];
    int n0 = blockIdx.x * 32, k0 = blockIdx.y * 32;
    int tx = threadIdx.x, ty = threadIdx.y;   // 32 x 8
#pragma unroll
    for (int i = 0; i < 4; i++)
        t[ty + i * 8][tx] = W[(size_t)(k0 + ty + i * 8) * N + n0 + tx];
    __syncthreads();
#pragma unroll
    for (int i = 0; i < 4; i++)
        Wt[(size_t)(n0 + ty + i * 8) * K + k0 + tx] =
            __float2half_rn(t[tx][ty + i * 8]);
}

// concat bq|bkv per layer into g_bqkv
__global__ void bias_prep(const float* __restrict__ bq,
                          const float* __restrict__ bkv,
                          float* __restrict__ out)
{
    int l = blockIdx.x;
    for (int j = threadIdx.x; j < QKVN; j += blockDim.x)
        out[l * QKVN + j] = (j < DIM) ? bq[l * DIM + j]
                                      : bkv[l * 2 * DIM + (j - DIM)];
}

// ---------------- LayerNorm (fp16 output) ------------------------------------
__global__ __launch_bounds__(128) void ln_kernel(
    const float* __restrict__ x, const float* __restrict__ g,
    const float* __restrict__ b, __half* __restrict__ y)
{
    int tok = blockIdx.x;
    const float4* xp = reinterpret_cast<const float4*>(x + (size_t)tok * DIM);
    int tid = threadIdx.x;

    float4 v = xp[tid];
    float s = v.x + v.y + v.z + v.w;

    __shared__ float red1[4], red2[4];
#pragma unroll
    for (int o = 16; o > 0; o >>= 1) s += __shfl_xor_sync(0xffffffffu, s, o);
    if ((tid & 31) == 0) red1[tid >> 5] = s;
    __syncthreads();
    float mean = (red1[0] + red1[1] + red1[2] + red1[3]) * (1.f / DIM);

    float dx = v.x - mean, dy = v.y - mean, dz = v.z - mean, dw = v.w - mean;
    float s2 = dx * dx + dy * dy + dz * dz + dw * dw;
#pragma unroll
    for (int o = 16; o > 0; o >>= 1) s2 += __shfl_xor_sync(0xffffffffu, s2, o);
    if ((tid & 31) == 0) red2[tid >> 5] = s2;
    __syncthreads();
    float var  = (red2[0] + red2[1] + red2[2] + red2[3]) * (1.f / DIM);
    float rstd = rsqrtf(var + 1e-5f);

    int c = tid * 4;
    float4 gg = reinterpret_cast<const float4*>(g)[tid];
    float4 bb = reinterpret_cast<const float4*>(b)[tid];
    float r0 = dx * rstd * gg.x + bb.x;
    float r1 = dy * rstd * gg.y + bb.y;
    float r2 = dz * rstd * gg.z + bb.z;
    float r3 = dw * rstd * gg.w + bb.w;
    __half2* yp2 = reinterpret_cast<__half2*>(y + (size_t)tok * DIM + c);
    yp2[0] = __floats2half2_rn(r0, r1);
    yp2[1] = __floats2half2_rn(r2, r3);
}

// ---------------- tensor-core fp16 GEMM --------------------------------------
// C[M,N] = A[M,K] @ Wt[N,K]^T + bias; epi: bias(fp16) / res-add(f32) / gelu(fp16)
// CTA 256x128, BK=64, 512 threads (16 warps, warp tile 32x64), 3-stage cp.async.
#define EPI_BIAS 0
#define EPI_RES  1
#define EPI_GELU 2

#define RSB    144                              // smem row stride bytes (64h + pad)
#define ATILE  (256 * RSB)                      // 36864 B
#define BTILE  (128 * RSB)                      // 18432 B
#define STAGEB (ATILE + BTILE)                  // 55296 B
#define GEMM_SMEM (3 * STAGEB)                  // 165888 B

__global__ __launch_bounds__(512, 1) void gemm_tc(
    const __half* __restrict__ A, const __half* __restrict__ Wt,
    const float* __restrict__ bias, const float* __restrict__ res,
    void* __restrict__ outP, int N, int K, int epi)
{
    extern __shared__ char smem[];
    uint32_t sbase = smem_u32(smem);

    int tid = threadIdx.x;
    int wid = tid >> 5, lane = tid & 31;
    int gq = lane >> 2, tq = lane & 3;
    int wm = wid >> 1, wn = wid & 1;           // warp: rows wm*32, cols wn*64
    int bn = blockIdx.x * 128, bm = blockIdx.y * 256;

    // ldmatrix lane offsets (bytes within stage)
    int t8 = lane >> 3, l8 = lane & 7;
    uint32_t a_off = (uint32_t)((wm * 32 + (t8 & 1) * 8 + l8) * RSB
                                + (t8 >> 1) * 16);
    uint32_t b_off = (uint32_t)(ATILE + (wn * 64 + (t8 >> 1) * 8 + l8) * RSB
                                + (t8 & 1) * 16);

    float acc[2][8][4];
#pragma unroll
    for (int mt = 0; mt < 2; mt++)
#pragma unroll
        for (int nt = 0; nt < 8; nt++)
#pragma unroll
            for (int r = 0; r < 4; r++) acc[mt][nt][r] = 0.f;

    const int NKB = K >> 6;                     // BK = 64

    // loader: A 256 rows x 8 chunks(16B), B 128 rows x 8 chunks
    int l_row = tid >> 3, l_c = tid & 7;        // base row 0..63, chunk 0..7

#define LOAD_STAGE(kb, stg) do {                                               \
    uint32_t sS = sbase + (uint32_t)(stg) * STAGEB;                            \
    const __half* gA = A  + (size_t)(bm + l_row) * K + (kb) * 64 + l_c * 8;    \
    const __half* gB = Wt + (size_t)(bn + l_row) * K + (kb) * 64 + l_c * 8;    \
    uint32_t dof = (uint32_t)(l_row * RSB + l_c * 16);                         \
    _Pragma("unroll")                                                          \
    for (int i = 0; i < 4; i++)                                                \
        asm volatile("cp.async.cg.shared.global [%0], [%1], 16;"               \
            :: "r"(sS + dof + i * 64 * RSB), "l"(gA + (size_t)i * 64 * K));    \
    _Pragma("unroll")                                                          \
    for (int i = 0; i < 2; i++)                                                \
        asm volatile("cp.async.cg.shared.global [%0], [%1], 16;"               \
            :: "r"(sS + ATILE + dof + i * 64 * RSB),                           \
               "l"(gB + (size_t)i * 64 * K));                                  \
} while (0)

    LOAD_STAGE(0, 0);
    asm volatile("cp.async.commit_group;");
    LOAD_STAGE(1, 1);
    asm volatile("cp.async.commit_group;");

    int stg = 0;
    for (int kb = 0; kb < NKB; kb++) {
        if (kb == NKB - 1) asm volatile("cp.async.wait_group 0;");
        else               asm volatile("cp.async.wait_group 1;");
        __syncthreads();
        if (kb + 2 < NKB) {
            int ns = stg + 2; if (ns >= 3) ns -= 3;
            LOAD_STAGE(kb + 2, ns);
            asm volatile("cp.async.commit_group;");
        }
        uint32_t sS = sbase + (uint32_t)stg * STAGEB;
#pragma unroll
        for (int ks = 0; ks < 4; ks++) {
            uint32_t af[2][4];
            ldmx4(af[0], sS + a_off + ks * 32);
            ldmx4(af[1], sS + a_off + ks * 32 + 16 * RSB);
            uint32_t bf[4][4];
#pragma unroll
            for (int p = 0; p < 4; p++)
                ldmx4(bf[p], sS + b_off + ks * 32 + p * 16 * RSB);
#pragma unroll
            for (int p = 0; p < 4; p++) {
                mma_f16(acc[0][2 * p],     af[0], bf[p][0], bf[p][1]);
                mma_f16(acc[1][2 * p],     af[1], bf[p][0], bf[p][1]);
                mma_f16(acc[0][2 * p + 1], af[0], bf[p][2], bf[p][3]);
                mma_f16(acc[1][2 * p + 1], af[1], bf[p][2], bf[p][3]);
            }
        }
        if (++stg == 3) stg = 0;
    }

    // ---- epilogue ----------------------------------------------------------
    float*  outF = reinterpret_cast<float*>(outP);
    __half* outH = reinterpret_cast<__half*>(outP);
#pragma unroll
    for (int mt = 0; mt < 2; mt++) {
        int row0 = bm + wm * 32 + mt * 16 + gq;
        int row1 = row0 + 8;
#pragma unroll
        for (int nt = 0; nt < 8; nt++) {
            int col = bn + wn * 64 + nt * 8 + 2 * tq;
            float2 bc = *reinterpret_cast<const float2*>(bias + col);
            float v00 = acc[mt][nt][0] + bc.x;
            float v01 = acc[mt][nt][1] + bc.y;
            float v10 = acc[mt][nt][2] + bc.x;
            float v11 = acc[mt][nt][3] + bc.y;
            if (epi == EPI_RES) {
                float2 r0 = *reinterpret_cast<const float2*>(
                    res + (size_t)row0 * N + col);
                float2 r1 = *reinterpret_cast<const float2*>(
                    res + (size_t)row1 * N + col);
                *reinterpret_cast<float2*>(outF + (size_t)row0 * N + col) =
                    make_float2(v00 + r0.x, v01 + r0.y);
                *reinterpret_cast<float2*>(outF + (size_t)row1 * N + col) =
                    make_float2(v10 + r1.x, v11 + r1.y);
            } else if (epi == EPI_GELU) {
                const float K0 = 0.7978845608028654f, K1 = 0.044715f;
                v00 = 0.5f * v00 * (1.f + tanhf(K0 * (v00 + K1 * v00 * v00 * v00)));
                v01 = 0.5f * v01 * (1.f + tanhf(K0 * (v01 + K1 * v01 * v01 * v01)));
                v10 = 0.5f * v10 * (1.f + tanhf(K0 * (v10 + K1 * v10 * v10 * v10)));
                v11 = 0.5f * v11 * (1.f + tanhf(K0 * (v11 + K1 * v11 * v11 * v11)));
                *reinterpret_cast<__half2*>(outH + (size_t)row0 * N + col) =
                    __floats2half2_rn(v00, v01);
                *reinterpret_cast<__half2*>(outH + (size_t)row1 * N + col) =
                    __floats2half2_rn(v10, v11);
            } else {
                *reinterpret_cast<__half2*>(outH + (size_t)row0 * N + col) =
                    __floats2half2_rn(v00, v01);
                *reinterpret_cast<__half2*>(outH + (size_t)row1 * N + col) =
                    __floats2half2_rn(v10, v11);
            }
        }
    }
}

// ---------------- Windowed attention (reads fused QKV) -----------------------
__global__ __launch_bounds__(64) void attn_kernel(
    const __half* __restrict__ qkv,
    const float* __restrict__ table, __half* __restrict__ out)
{
    __shared__ float Ks[64][DK];
    __shared__ float Vs[64][DK];
    __shared__ float tbl[TBL];
    __shared__ int   cnts[64];

    int w    = blockIdx.x;
    int head = blockIdx.y;
    int b  = w >> 6;
    int wi = w & 63;
    int wh = wi >> 3, wwc = wi & 7;
    int e  = threadIdx.x;
    int r  = e >> 3, c = e & 7;

    int gh = (wh * 8 + r + SHIFT) & 63;
    int gw = (wwc * 8 + c + SHIFT) & 63;
    int tok = (b * 64 + gh) * 64 + gw;

    const __half* qp = qkv + (size_t)tok * QKVN + head * DK;
    const __half* kp = qp + DIM;          // K at +512
    const __half* vp = qp + 2 * DIM;      // V at +1024

    float qreg[DK];
#pragma unroll
    for (int d = 0; d < DK; d++) {
        qreg[d]  = __half2float(qp[d]);
        Ks[e][d] = __half2float(kp[d]);
        Vs[e][d] = __half2float(vp[d]);
    }
    int ii = wh * 8 + r, jj = wwc * 8 + c;
    int ridi = (ii < HH - WS) ? 0 : ((ii < HH - SHIFT) ? 1 : 2);
    int ridj = (jj < WW_ - WS) ? 0 : ((jj < WW_ - SHIFT) ? 1 : 2);
    cnts[e] = ridi * 3 + ridj;
    for (int t = e; t < TBL; t += 64) tbl[t] = table[t * NHEAD + head];
    __syncthreads();

    const float SCALE = 0.17677669529663687f;  // 1/sqrt(32)
    float s[64];
    float mx = -1e30f;
    int mycnt = cnts[e];
#pragma unroll 4
    for (int kk = 0; kk < 64; kk++) {
        float acc = 0.f;
#pragma unroll
        for (int d = 0; d < DK; d++) acc += qreg[d] * Ks[kk][d];
        int kr = kk >> 3, kc = kk & 7;
        acc = acc * SCALE + tbl[(r - kr + 7) * 15 + (c - kc + 7)];
        if (mycnt != cnts[kk]) acc = -1e9f;
        s[kk] = acc;
        mx = fmaxf(mx, acc);
    }
    float sum = 0.f;
#pragma unroll 4
    for (int kk = 0; kk < 64; kk++) { s[kk] = expf(s[kk] - mx); sum += s[kk]; }
    float inv = 1.f / sum;

    float o[DK];
#pragma unroll
    for (int d = 0; d < DK; d++) o[d] = 0.f;
#pragma unroll 4
    for (int kk = 0; kk < 64; kk++) {
        float p = s[kk];
#pragma unroll
        for (int d = 0; d < DK; d++) o[d] += p * Vs[kk][d];
    }
    __half* op = out + (size_t)tok * DIM + head * DK;
#pragma unroll
    for (int d = 0; d < DK; d++) op[d] = __float2half_rn(o[d] * inv);
}

// ---------------- launch ----------------------------------------------------
extern "C" void kernel_launch(void* const* d_in, const int* in_sizes, int n_in,
                              void* d_out, int out_size)
{
    const float* x_in  = (const float*)d_in[0];
    const float* Wq   = (const float*)d_in[3];
    const float* bq   = (const float*)d_in[4];
    const float* Wkv  = (const float*)d_in[5];
    const float* bkv  = (const float*)d_in[6];
    const float* Wo   = (const float*)d_in[7];
    const float* bo   = (const float*)d_in[8];
    const float* rtab = (const float*)d_in[9];
    const float* ln1g = (const float*)d_in[10];
    const float* ln1b = (const float*)d_in[11];
    const float* ln2g = (const float*)d_in[12];
    const float* ln2b = (const float*)d_in[13];
    const float* W1   = (const float*)d_in[14];
    const float* b1   = (const float*)d_in[15];
    const float* W2   = (const float*)d_in[16];
    const float* b2   = (const float*)d_in[17];

    float *gx, *gbqkv;
    __half *gxn, *gqkv, *gat, *ghid;
    __half *wqkvT, *woT, *w1T, *w2T;
    cudaGetSymbolAddress((void**)&gx,    g_x);
    cudaGetSymbolAddress((void**)&gxn,   g_xn);
    cudaGetSymbolAddress((void**)&gqkv,  g_qkv);
    cudaGetSymbolAddress((void**)&gat,   g_at);
    cudaGetSymbolAddress((void**)&ghid,  g_h);
    cudaGetSymbolAddress((void**)&wqkvT, g_wqkvT);
    cudaGetSymbolAddress((void**)&gbqkv, g_bqkv);
    cudaGetSymbolAddress((void**)&woT,   g_woT);
    cudaGetSymbolAddress((void**)&w1T,   g_w1T);
    cudaGetSymbolAddress((void**)&w2T,   g_w2T);

    cudaFuncSetAttribute(gemm_tc,
        cudaFuncAttributeMaxDynamicSharedMemorySize, GEMM_SMEM);

    cudaMemcpyAsync(gx, x_in, (size_t)NTOK * DIM * sizeof(float),
                    cudaMemcpyDeviceToDevice);

    // weight transposes (fp16) + fused qkv bias
    dim3 tb(32, 8);
    bias_prep<<<LAYERS, 512>>>(bq, bkv, gbqkv);
    for (int i = 0; i < LAYERS; i++) {
        __half* wqkvT_i = wqkvT + (size_t)i * QKVN * DIM;
        wt_prep<<<dim3(16, 16), tb>>>(Wq  + (size_t)i*DIM*DIM,   wqkvT_i,                DIM, DIM);
        wt_prep<<<dim3(32, 16), tb>>>(Wkv + (size_t)i*DIM*2*DIM, wqkvT_i + (size_t)DIM*DIM, DIM, 2*DIM);
        wt_prep<<<dim3(16, 16), tb>>>(Wo  + (size_t)i*DIM*DIM,   woT + (size_t)i*DIM*DIM,   DIM, DIM);
        wt_prep<<<dim3(64, 16), tb>>>(W1  + (size_t)i*DIM*4*DIM, w1T + (size_t)i*4*DIM*DIM, DIM, 4*DIM);
        wt_prep<<<dim3(16, 64), tb>>>(W2  + (size_t)i*4*DIM*DIM, w2T + (size_t)i*DIM*4*DIM, 4*DIM, DIM);
    }

    for (int i = 0; i < LAYERS; i++) {
        // LN1
        ln_kernel<<<NTOK, 128>>>(gx, ln1g + i * DIM, ln1b + i * DIM, gxn);
        // QKV = xn @ [Wq|Wkv] + [bq|bkv]   (fused, N=1536)
        gemm_tc<<<dim3(QKVN/128, NTOK/256), 512, GEMM_SMEM>>>(
            gxn, wqkvT + (size_t)i*QKVN*DIM, gbqkv + i*QKVN, nullptr, gqkv,
            QKVN, DIM, EPI_BIAS);
        // windowed attention
        attn_kernel<<<dim3(BATCH * 64, NHEAD), 64>>>(
            gqkv, rtab + (size_t)i * TBL * NHEAD, gat);
        // x = x + attn @ Wo + bo
        gemm_tc<<<dim3(DIM/128, NTOK/256), 512, GEMM_SMEM>>>(
            gat, woT + (size_t)i*DIM*DIM, bo + i*DIM, gx, gx,
            DIM, DIM, EPI_RES);
        // LN2
        ln_kernel<<<NTOK, 128>>>(gx, ln2g + i * DIM, ln2b + i * DIM, gxn);
        // h = gelu(xn @ W1 + b1)
        gemm_tc<<<dim3(4*DIM/128, NTOK/256), 512, GEMM_SMEM>>>(
            gxn, w1T + (size_t)i*4*DIM*DIM, b1 + i*4*DIM, nullptr, ghid,
            4*DIM, DIM, EPI_GELU);
        // x = x + h @ W2 + b2
        gemm_tc<<<dim3(DIM/128, NTOK/256), 512, GEMM_SMEM>>>(
            ghid, w2T + (size_t)i*DIM*4*DIM, b2 + i*DIM, gx, gx,
            DIM, 4*DIM, EPI_RES);
    }

    cudaMemcpyAsync(d_out, gx, (size_t)NTOK * DIM * sizeof(float),
                    cudaMemcpyDeviceToDevice);
}